// round 3
// baseline (speedup 1.0000x reference)
#include <cuda_runtime.h>
#include <math.h>

// Problem constants
#define BB   2
#define SS   2048
#define HH   1024
#define NH   16
#define HD   64
#define MTOT (BB*SS)   // 4096

// Scratch (device globals: allocation-free per harness rules)
__device__ float g_Qp[BB*NH*SS*HD];   // [B, nh, S, hd]
__device__ float g_Kp[BB*NH*SS*HD];
__device__ float g_Vp[BB*NH*SS*HD];
__device__ float g_Ctx[BB*SS*HH];     // attention output, [B, S, H]

// ---------------------------------------------------------------------------
// NT GEMM: C[m,n] = sum_k A[m,k] * W[n,k] + bias[n]
// A: [MTOT, HH] row-major, W: [HH, HH] row-major (Linear weight, used as W^T)
// MODE 0: C row-major [MTOT, HH]
// MODE 1: C written to [B, nh, S, hd] split-head layout
// Tile 64x64, BK=32, 256 threads, 4x4 micro-tile with strided (tx+16j) cols.
// ---------------------------------------------------------------------------
template<int MODE>
__global__ __launch_bounds__(256, 2)
void gemm_nt_kernel(const float* __restrict__ A,
                    const float* __restrict__ W,
                    const float* __restrict__ bias,
                    float* __restrict__ C)
{
    const int LD = 36;                  // 36 % 32 = 4 -> 2-way max on strided reads, 16B aligned
    __shared__ float As[64 * LD];
    __shared__ float Ws[64 * LD];

    const int tid = threadIdx.x;
    const int tx = tid & 15;
    const int ty = tid >> 4;
    const int m0 = blockIdx.y * 64;
    const int n0 = blockIdx.x * 64;

    float acc[4][4] = {};

    for (int k0 = 0; k0 < HH; k0 += 32) {
        __syncthreads();
        // Load 64x32 tiles of A and W (float4, fully coalesced: 8 lanes/row cover 128B)
        #pragma unroll
        for (int it = 0; it < 2; it++) {
            int f   = tid + it * 256;       // 0..511
            int row = f >> 3;               // 0..63
            int kc  = (f & 7) << 2;         // 0,4,...,28
            float4 va = *(const float4*)&A[(size_t)(m0 + row) * HH + k0 + kc];
            *(float4*)&As[row * LD + kc] = va;
            float4 vw = *(const float4*)&W[(size_t)(n0 + row) * HH + k0 + kc];
            *(float4*)&Ws[row * LD + kc] = vw;
        }
        __syncthreads();

        #pragma unroll
        for (int kk = 0; kk < 32; kk += 4) {
            float4 a4[4], w4[4];
            #pragma unroll
            for (int i = 0; i < 4; i++)
                a4[i] = *(const float4*)&As[(ty + 16 * i) * LD + kk];   // 2 addrs/warp: broadcast
            #pragma unroll
            for (int j = 0; j < 4; j++)
                w4[j] = *(const float4*)&Ws[(tx + 16 * j) * LD + kk];   // <=2-way
            #pragma unroll
            for (int i = 0; i < 4; i++) {
                #pragma unroll
                for (int j = 0; j < 4; j++) {
                    acc[i][j] += a4[i].x * w4[j].x;
                    acc[i][j] += a4[i].y * w4[j].y;
                    acc[i][j] += a4[i].z * w4[j].z;
                    acc[i][j] += a4[i].w * w4[j].w;
                }
            }
        }
    }

    // Epilogue
    #pragma unroll
    for (int j = 0; j < 4; j++) {
        int n = n0 + tx + 16 * j;
        float bb = bias[n];
        #pragma unroll
        for (int i = 0; i < 4; i++) {
            int m = m0 + ty + 16 * i;
            float v = acc[i][j] + bb;
            if (MODE == 0) {
                C[(size_t)m * HH + n] = v;
            } else {
                int b = m >> 11;        // m / 2048
                int s = m & 2047;
                int h = n >> 6;         // n / 64  (tile width == hd, so one head per n-tile)
                int d = n & 63;
                C[(((size_t)(b * NH + h)) * SS + s) * HD + d] = v;
            }
        }
    }
}

// ---------------------------------------------------------------------------
// Flash attention (fp32): one block per (bh, q-tile of 64 rows).
// Smem: Q (plain), K (XOR-swizzled, reused for P), V (plain). 48KB total.
// ---------------------------------------------------------------------------
__global__ __launch_bounds__(256, 2)
void attn_kernel()
{
    __shared__ float Qs [64 * 64];   // [q][d], scaled by 1/sqrt(hd)
    __shared__ float KPs[64 * 64];   // K: [k][d] XOR-swizzled; reused as P: [q][k] plain
    __shared__ float Vs [64 * 64];   // [k][d]

    const int tid = threadIdx.x;
    const int tx = tid & 15;
    const int ty = tid >> 4;
    const int qt = blockIdx.x;       // 0..31
    const int bh = blockIdx.y;       // 0..31

    const float* Qb = g_Qp + (size_t)bh * SS * HD + (size_t)qt * 64 * HD;
    const float* Kb = g_Kp + (size_t)bh * SS * HD;
    const float* Vb = g_Vp + (size_t)bh * SS * HD;

    // Load Q tile once, fold in softmax scale 1/sqrt(64) = 0.125
    #pragma unroll
    for (int it = 0; it < 4; it++) {
        int f   = tid + it * 256;    // float4 index 0..1023
        int row = f >> 4;
        int dc  = (f & 15) << 2;
        float4 v = *(const float4*)&Qb[(size_t)row * HD + dc];
        v.x *= 0.125f; v.y *= 0.125f; v.z *= 0.125f; v.w *= 0.125f;
        *(float4*)&Qs[row * 64 + dc] = v;
    }

    float o[4][4] = {};
    float mrow[4], lrow[4];
    #pragma unroll
    for (int i = 0; i < 4; i++) { mrow[i] = -1e30f; lrow[i] = 0.0f; }

    for (int kt = 0; kt < SS / 64; kt++) {
        __syncthreads();   // prev GEMM2 done with KPs/Vs (and makes Qs visible on iter 0)
        const float* Kt = Kb + (size_t)kt * 64 * HD;
        const float* Vt = Vb + (size_t)kt * 64 * HD;
        #pragma unroll
        for (int it = 0; it < 4; it++) {
            int f   = tid + it * 256;
            int row = f >> 4;
            int c4  = f & 15;
            float4 kv = *(const float4*)&Kt[(size_t)row * HD + c4 * 4];
            int sc4 = c4 ^ (row & 15);                    // XOR swizzle -> conflict-free reads
            *(float4*)&KPs[row * 64 + sc4 * 4] = kv;
            float4 vv = *(const float4*)&Vt[(size_t)row * HD + c4 * 4];
            *(float4*)&Vs[row * 64 + c4 * 4] = vv;
        }
        __syncthreads();

        // GEMM1: sc[i][j] = sum_d Q[q_i][d] * K[k_j][d],  q_i=ty+16i, k_j=tx+16j
        float sc[4][4] = {};
        #pragma unroll
        for (int d4 = 0; d4 < 16; d4++) {
            float4 a4[4], b4[4];
            #pragma unroll
            for (int i = 0; i < 4; i++)
                a4[i] = *(const float4*)&Qs[(ty + 16 * i) * 64 + d4 * 4];
            #pragma unroll
            for (int j = 0; j < 4; j++) {
                int k = tx + 16 * j;                      // k & 15 == tx
                b4[j] = *(const float4*)&KPs[k * 64 + (d4 ^ tx) * 4];
            }
            #pragma unroll
            for (int i = 0; i < 4; i++) {
                #pragma unroll
                for (int j = 0; j < 4; j++) {
                    sc[i][j] += a4[i].x * b4[j].x;
                    sc[i][j] += a4[i].y * b4[j].y;
                    sc[i][j] += a4[i].z * b4[j].z;
                    sc[i][j] += a4[i].w * b4[j].w;
                }
            }
        }
        __syncthreads();   // all K reads complete before KPs is overwritten by P

        // Online softmax (row reduction across the 16 tx lanes via shfl.xor)
        #pragma unroll
        for (int i = 0; i < 4; i++) {
            float tm = fmaxf(fmaxf(sc[i][0], sc[i][1]), fmaxf(sc[i][2], sc[i][3]));
            #pragma unroll
            for (int off = 8; off >= 1; off >>= 1)
                tm = fmaxf(tm, __shfl_xor_sync(0xffffffffu, tm, off));
            float mn   = fmaxf(mrow[i], tm);
            float corr = __expf(mrow[i] - mn);
            mrow[i] = mn;
            float rs = 0.0f;
            #pragma unroll
            for (int j = 0; j < 4; j++) {
                float p = __expf(sc[i][j] - mn);
                sc[i][j] = p;
                rs += p;
            }
            #pragma unroll
            for (int off = 8; off >= 1; off >>= 1)
                rs += __shfl_xor_sync(0xffffffffu, rs, off);
            lrow[i] = lrow[i] * corr + rs;
            #pragma unroll
            for (int j = 0; j < 4; j++) o[i][j] *= corr;
            #pragma unroll
            for (int j = 0; j < 4; j++)
                KPs[(ty + 16 * i) * 64 + tx + 16 * j] = sc[i][j];   // P, plain layout
        }
        __syncthreads();

        // GEMM2: o[i][j] += sum_k P[q_i][k] * V[k][d_j],  d_j = tx+16j
        #pragma unroll
        for (int k4 = 0; k4 < 16; k4++) {
            float4 p4[4];
            #pragma unroll
            for (int i = 0; i < 4; i++)
                p4[i] = *(const float4*)&KPs[(ty + 16 * i) * 64 + k4 * 4];
            #pragma unroll
            for (int kk = 0; kk < 4; kk++) {
                float v[4];
                #pragma unroll
                for (int j = 0; j < 4; j++)
                    v[j] = Vs[(k4 * 4 + kk) * 64 + tx + 16 * j];    // stride-1 across lanes
                #pragma unroll
                for (int i = 0; i < 4; i++) {
                    float p = (kk == 0) ? p4[i].x : (kk == 1) ? p4[i].y
                            : (kk == 2) ? p4[i].z : p4[i].w;
                    #pragma unroll
                    for (int j = 0; j < 4; j++)
                        o[i][j] += p * v[j];
                }
            }
        }
    }

    // Epilogue: normalize by l, write to [B, S, H]
    const int b = bh >> 4, h = bh & 15;
    #pragma unroll
    for (int i = 0; i < 4; i++) {
        float inv = 1.0f / lrow[i];
        int q = qt * 64 + ty + 16 * i;
        #pragma unroll
        for (int j = 0; j < 4; j++) {
            int d = tx + 16 * j;
            g_Ctx[((size_t)(b * SS + q)) * HH + h * HD + d] = o[i][j] * inv;
        }
    }
}

// ---------------------------------------------------------------------------
extern "C" void kernel_launch(void* const* d_in, const int* in_sizes, int n_in,
                              void* d_out, int out_size)
{
    const float* q  = (const float*)d_in[0];
    const float* k  = (const float*)d_in[1];
    const float* v  = (const float*)d_in[2];
    const float* Wq = (const float*)d_in[3];
    const float* bq = (const float*)d_in[4];
    const float* Wk = (const float*)d_in[5];
    const float* bk = (const float*)d_in[6];
    const float* Wv = (const float*)d_in[7];
    const float* bv = (const float*)d_in[8];
    const float* Wo = (const float*)d_in[9];
    const float* bo = (const float*)d_in[10];
    float* out = (float*)d_out;

    float *Qp, *Kp, *Vp, *Ctx;
    cudaGetSymbolAddress((void**)&Qp,  g_Qp);
    cudaGetSymbolAddress((void**)&Kp,  g_Kp);
    cudaGetSymbolAddress((void**)&Vp,  g_Vp);
    cudaGetSymbolAddress((void**)&Ctx, g_Ctx);

    dim3 blk(256);
    dim3 gg(HH / 64, MTOT / 64);     // (16, 64)

    gemm_nt_kernel<1><<<gg, blk>>>(q, Wq, bq, Qp);
    gemm_nt_kernel<1><<<gg, blk>>>(k, Wk, bk, Kp);
    gemm_nt_kernel<1><<<gg, blk>>>(v, Wv, bv, Vp);
    attn_kernel<<<dim3(SS / 64, BB * NH), blk>>>();
    gemm_nt_kernel<0><<<gg, blk>>>(Ctx, Wo, bo, out);
}

// round 6
// speedup vs baseline: 1.5026x; 1.5026x over previous
#include <cuda_runtime.h>
#include <cuda_bf16.h>
#include <cstdint>
#include <math.h>

// Problem constants
#define BB   2
#define SS   2048
#define HH   1024
#define NH   16
#define HD   64
#define MTOT (BB*SS)   // 4096

// Scratch (device globals: allocation-free per harness rules)
__device__ float g_Qp[BB*NH*SS*HD];   // [B, nh, S, hd]
__device__ float g_Kp[BB*NH*SS*HD];
__device__ float g_Vp[BB*NH*SS*HD];
__device__ float g_Ctx[BB*SS*HH];     // attention output, [B, S, H]

// bf16 split buffers (reused sequentially across the 4 GEMMs)
__device__ __nv_bfloat16 g_Ahi[MTOT*HH];
__device__ __nv_bfloat16 g_Alo[MTOT*HH];
__device__ __nv_bfloat16 g_Whi[HH*HH];
__device__ __nv_bfloat16 g_Wlo[HH*HH];

// ---------------------------------------------------------------------------
// PTX helpers (inline functions, not macros)
// ---------------------------------------------------------------------------
__device__ __forceinline__ void cp16(unsigned dst, const void* src) {
    asm volatile("cp.async.cg.shared.global [%0], [%1], 16;"
                 :: "r"(dst), "l"(src));
}

__device__ __forceinline__ void cp_commit_wait() {
    asm volatile("cp.async.commit_group;");
    asm volatile("cp.async.wait_group 0;");
}

__device__ __forceinline__ void ldsm4(unsigned (&r)[4], unsigned addr) {
    asm volatile("ldmatrix.sync.aligned.m8n8.x4.shared.b16 {%0,%1,%2,%3}, [%4];"
                 : "=r"(r[0]), "=r"(r[1]), "=r"(r[2]), "=r"(r[3]) : "r"(addr));
}

__device__ __forceinline__ void mma16816(float (&c)[4], const unsigned (&a)[4],
                                         unsigned b0, unsigned b1) {
    asm volatile("mma.sync.aligned.m16n8k16.row.col.f32.bf16.bf16.f32 "
                 "{%0,%1,%2,%3},{%4,%5,%6,%7},{%8,%9},{%0,%1,%2,%3};"
                 : "+f"(c[0]), "+f"(c[1]), "+f"(c[2]), "+f"(c[3])
                 : "r"(a[0]), "r"(a[1]), "r"(a[2]), "r"(a[3]), "r"(b0), "r"(b1));
}

// ---------------------------------------------------------------------------
// fp32 -> (bf16 hi, bf16 lo) split.  Grid covers n/4 float4 elements exactly.
// ---------------------------------------------------------------------------
__global__ void cvt_split_kernel(const float* __restrict__ x,
                                 __nv_bfloat16* __restrict__ hi,
                                 __nv_bfloat16* __restrict__ lo)
{
    int i = blockIdx.x * blockDim.x + threadIdx.x;   // float4 index
    float4 v = ((const float4*)x)[i];

    __nv_bfloat16 h0 = __float2bfloat16(v.x);
    __nv_bfloat16 h1 = __float2bfloat16(v.y);
    __nv_bfloat16 h2 = __float2bfloat16(v.z);
    __nv_bfloat16 h3 = __float2bfloat16(v.w);
    __nv_bfloat16 l0 = __float2bfloat16(v.x - __bfloat162float(h0));
    __nv_bfloat16 l1 = __float2bfloat16(v.y - __bfloat162float(h1));
    __nv_bfloat16 l2 = __float2bfloat16(v.z - __bfloat162float(h2));
    __nv_bfloat16 l3 = __float2bfloat16(v.w - __bfloat162float(h3));

    __nv_bfloat162* hp = (__nv_bfloat162*)hi;
    __nv_bfloat162* lp = (__nv_bfloat162*)lo;
    hp[2*i]   = __nv_bfloat162(h0, h1);
    hp[2*i+1] = __nv_bfloat162(h2, h3);
    lp[2*i]   = __nv_bfloat162(l0, l1);
    lp[2*i+1] = __nv_bfloat162(l2, l3);
}

// ---------------------------------------------------------------------------
// Tensor-core NT GEMM via bf16 split: C[m,n] = sum_k A[m,k]*W[n,k] + bias[n]
//   C approximated by Ahi*Whi + Ahi*Wlo + Alo*Whi, fp32 accumulation.
// Block tile 128(M) x 64(N), K-chunk 64, 8 warps (4x2), warp tile 32x32.
// smem: XOR-swizzled 128B rows -> conflict-free ldmatrix.
// MODE 0: C row-major [MTOT,HH].  MODE 1: [B,nh,S,hd] split-head layout.
// ---------------------------------------------------------------------------
template<int MODE>
__global__ __launch_bounds__(256, 2)
void gemm_mma_kernel(const __nv_bfloat16* __restrict__ Ahi,
                     const __nv_bfloat16* __restrict__ Alo,
                     const __nv_bfloat16* __restrict__ Whi,
                     const __nv_bfloat16* __restrict__ Wlo,
                     const float* __restrict__ bias,
                     float* __restrict__ C)
{
    // 48KB static smem: Ahi 16K | Alo 16K | Bhi 8K | Blo 8K
    __shared__ __align__(128) char sm[49152];
    const unsigned sbase = (unsigned)__cvta_generic_to_shared(sm);
    const unsigned sAhi = sbase;
    const unsigned sAlo = sbase + 16384;
    const unsigned sBhi = sbase + 32768;
    const unsigned sBlo = sbase + 40960;

    const int tid  = threadIdx.x;
    const int lane = tid & 31;
    const int warp = tid >> 5;
    const int wm0  = (warp >> 1) * 32;       // warp M origin within block (0,32,64,96)
    const int wn0  = (warp & 1) * 32;        // warp N origin within block (0,32)
    const int m0   = blockIdx.y * 128;
    const int n0   = blockIdx.x * 64;

    float acc[2][4][4] = {};                 // [mt][nt][frag]

    // ldmatrix lane->address components (constant over k loop)
    const int a_r   = lane & 15;             // A: row within 16
    const int a_kh  = lane >> 4;             // A: k half (0/1)
    const int b_r   = (lane & 7) + ((lane >> 4) << 3);   // B: n within 16
    const int b_kh  = (lane >> 3) & 1;       // B: k half

    for (int k0 = 0; k0 < HH; k0 += 64) {
        __syncthreads();   // previous chunk's ldmatrix reads complete

        // Stage A tiles: 128 rows x 64 bf16 (128B rows), hi & lo
        #pragma unroll
        for (int i = 0; i < 4; i++) {
            int e = tid + i * 256;
            int r = e >> 3, c = e & 7;
            unsigned soff = (unsigned)(r * 128 + ((c ^ (r & 7)) << 4));
            cp16(sAhi + soff, Ahi + (size_t)(m0 + r) * HH + k0 + c * 8);
            cp16(sAlo + soff, Alo + (size_t)(m0 + r) * HH + k0 + c * 8);
        }
        // Stage B tiles: 64 rows x 64 bf16, hi & lo
        #pragma unroll
        for (int i = 0; i < 2; i++) {
            int e = tid + i * 256;
            int r = e >> 3, c = e & 7;
            unsigned soff = (unsigned)(r * 128 + ((c ^ (r & 7)) << 4));
            cp16(sBhi + soff, Whi + (size_t)(n0 + r) * HH + k0 + c * 8);
            cp16(sBlo + soff, Wlo + (size_t)(n0 + r) * HH + k0 + c * 8);
        }
        cp_commit_wait();
        __syncthreads();

        #pragma unroll
        for (int kk = 0; kk < 4; kk++) {
            unsigned fAh[2][4], fAl[2][4], fBh[2][4], fBl[2][4];

            #pragma unroll
            for (int mt = 0; mt < 2; mt++) {
                int r = wm0 + mt * 16 + a_r;
                int c = kk * 2 + a_kh;
                unsigned off = (unsigned)(r * 128 + ((c ^ (r & 7)) << 4));
                ldsm4(fAh[mt], sAhi + off);
                ldsm4(fAl[mt], sAlo + off);
            }
            #pragma unroll
            for (int nt2 = 0; nt2 < 2; nt2++) {
                int r = wn0 + nt2 * 16 + b_r;
                int c = kk * 2 + b_kh;
                unsigned off = (unsigned)(r * 128 + ((c ^ (r & 7)) << 4));
                ldsm4(fBh[nt2], sBhi + off);
                ldsm4(fBl[nt2], sBlo + off);
            }
            #pragma unroll
            for (int mt = 0; mt < 2; mt++) {
                #pragma unroll
                for (int nt = 0; nt < 4; nt++) {
                    int n2 = nt >> 1, p = (nt & 1) * 2;
                    mma16816(acc[mt][nt], fAh[mt], fBh[n2][p], fBh[n2][p+1]); // hi*hi
                    mma16816(acc[mt][nt], fAh[mt], fBl[n2][p], fBl[n2][p+1]); // hi*lo
                    mma16816(acc[mt][nt], fAl[mt], fBh[n2][p], fBh[n2][p+1]); // lo*hi
                }
            }
        }
    }

    // Epilogue: C frag -> (row = g / g+8, col = 2q, 2q+1)
    const int g = lane >> 2, q = lane & 3;
    #pragma unroll
    for (int mt = 0; mt < 2; mt++) {
        #pragma unroll
        for (int nt = 0; nt < 4; nt++) {
            int col = n0 + wn0 + nt * 8 + q * 2;
            float b0 = bias[col], b1 = bias[col + 1];
            #pragma unroll
            for (int half = 0; half < 2; half++) {
                int row = m0 + wm0 + mt * 16 + g + half * 8;
                float v0 = acc[mt][nt][half * 2]     + b0;
                float v1 = acc[mt][nt][half * 2 + 1] + b1;
                if (MODE == 0) {
                    *(float2*)&C[(size_t)row * HH + col] = make_float2(v0, v1);
                } else {
                    int b = row >> 11, s = row & 2047;
                    int h = col >> 6,  d = col & 63;
                    *(float2*)&C[(((size_t)(b * NH + h)) * SS + s) * HD + d] =
                        make_float2(v0, v1);
                }
            }
        }
    }
}

// ---------------------------------------------------------------------------
// Flash attention (fp32): unchanged from Round 3 (at fp32 FFMA roofline).
// ---------------------------------------------------------------------------
__global__ __launch_bounds__(256, 2)
void attn_kernel()
{
    __shared__ float Qs [64 * 64];   // [q][d], scaled by 1/sqrt(hd)
    __shared__ float KPs[64 * 64];   // K: [k][d] XOR-swizzled; reused as P: [q][k] plain
    __shared__ float Vs [64 * 64];   // [k][d]

    const int tid = threadIdx.x;
    const int tx = tid & 15;
    const int ty = tid >> 4;
    const int qt = blockIdx.x;       // 0..31
    const int bh = blockIdx.y;       // 0..31

    const float* Qb = g_Qp + (size_t)bh * SS * HD + (size_t)qt * 64 * HD;
    const float* Kb = g_Kp + (size_t)bh * SS * HD;
    const float* Vb = g_Vp + (size_t)bh * SS * HD;

    #pragma unroll
    for (int it = 0; it < 4; it++) {
        int f   = tid + it * 256;
        int row = f >> 4;
        int dc  = (f & 15) << 2;
        float4 v = *(const float4*)&Qb[(size_t)row * HD + dc];
        v.x *= 0.125f; v.y *= 0.125f; v.z *= 0.125f; v.w *= 0.125f;
        *(float4*)&Qs[row * 64 + dc] = v;
    }

    float o[4][4] = {};
    float mrow[4], lrow[4];
    #pragma unroll
    for (int i = 0; i < 4; i++) { mrow[i] = -1e30f; lrow[i] = 0.0f; }

    for (int kt = 0; kt < SS / 64; kt++) {
        __syncthreads();
        const float* Kt = Kb + (size_t)kt * 64 * HD;
        const float* Vt = Vb + (size_t)kt * 64 * HD;
        #pragma unroll
        for (int it = 0; it < 4; it++) {
            int f   = tid + it * 256;
            int row = f >> 4;
            int c4  = f & 15;
            float4 kv = *(const float4*)&Kt[(size_t)row * HD + c4 * 4];
            int sc4 = c4 ^ (row & 15);
            *(float4*)&KPs[row * 64 + sc4 * 4] = kv;
            float4 vv = *(const float4*)&Vt[(size_t)row * HD + c4 * 4];
            *(float4*)&Vs[row * 64 + c4 * 4] = vv;
        }
        __syncthreads();

        float sc[4][4] = {};
        #pragma unroll
        for (int d4 = 0; d4 < 16; d4++) {
            float4 a4[4], b4[4];
            #pragma unroll
            for (int i = 0; i < 4; i++)
                a4[i] = *(const float4*)&Qs[(ty + 16 * i) * 64 + d4 * 4];
            #pragma unroll
            for (int j = 0; j < 4; j++) {
                int k = tx + 16 * j;
                b4[j] = *(const float4*)&KPs[k * 64 + (d4 ^ tx) * 4];
            }
            #pragma unroll
            for (int i = 0; i < 4; i++) {
                #pragma unroll
                for (int j = 0; j < 4; j++) {
                    sc[i][j] += a4[i].x * b4[j].x;
                    sc[i][j] += a4[i].y * b4[j].y;
                    sc[i][j] += a4[i].z * b4[j].z;
                    sc[i][j] += a4[i].w * b4[j].w;
                }
            }
        }
        __syncthreads();

        #pragma unroll
        for (int i = 0; i < 4; i++) {
            float tm = fmaxf(fmaxf(sc[i][0], sc[i][1]), fmaxf(sc[i][2], sc[i][3]));
            #pragma unroll
            for (int off = 8; off >= 1; off >>= 1)
                tm = fmaxf(tm, __shfl_xor_sync(0xffffffffu, tm, off));
            float mn   = fmaxf(mrow[i], tm);
            float corr = __expf(mrow[i] - mn);
            mrow[i] = mn;
            float rs = 0.0f;
            #pragma unroll
            for (int j = 0; j < 4; j++) {
                float p = __expf(sc[i][j] - mn);
                sc[i][j] = p;
                rs += p;
            }
            #pragma unroll
            for (int off = 8; off >= 1; off >>= 1)
                rs += __shfl_xor_sync(0xffffffffu, rs, off);
            lrow[i] = lrow[i] * corr + rs;
            #pragma unroll
            for (int j = 0; j < 4; j++) o[i][j] *= corr;
            #pragma unroll
            for (int j = 0; j < 4; j++)
                KPs[(ty + 16 * i) * 64 + tx + 16 * j] = sc[i][j];
        }
        __syncthreads();

        #pragma unroll
        for (int k4 = 0; k4 < 16; k4++) {
            float4 p4[4];
            #pragma unroll
            for (int i = 0; i < 4; i++)
                p4[i] = *(const float4*)&KPs[(ty + 16 * i) * 64 + k4 * 4];
            #pragma unroll
            for (int kk = 0; kk < 4; kk++) {
                float v[4];
                #pragma unroll
                for (int j = 0; j < 4; j++)
                    v[j] = Vs[(k4 * 4 + kk) * 64 + tx + 16 * j];
                #pragma unroll
                for (int i = 0; i < 4; i++) {
                    float p = (kk == 0) ? p4[i].x : (kk == 1) ? p4[i].y
                            : (kk == 2) ? p4[i].z : p4[i].w;
                    #pragma unroll
                    for (int j = 0; j < 4; j++)
                        o[i][j] += p * v[j];
                }
            }
        }
    }

    const int b = bh >> 4, h = bh & 15;
    #pragma unroll
    for (int i = 0; i < 4; i++) {
        float inv = 1.0f / lrow[i];
        int q = qt * 64 + ty + 16 * i;
        #pragma unroll
        for (int j = 0; j < 4; j++) {
            int d = tx + 16 * j;
            g_Ctx[((size_t)(b * SS + q)) * HH + h * HD + d] = o[i][j] * inv;
        }
    }
}

// ---------------------------------------------------------------------------
extern "C" void kernel_launch(void* const* d_in, const int* in_sizes, int n_in,
                              void* d_out, int out_size)
{
    const float* q  = (const float*)d_in[0];
    const float* k  = (const float*)d_in[1];
    const float* v  = (const float*)d_in[2];
    const float* Wq = (const float*)d_in[3];
    const float* bq = (const float*)d_in[4];
    const float* Wk = (const float*)d_in[5];
    const float* bk = (const float*)d_in[6];
    const float* Wv = (const float*)d_in[7];
    const float* bv = (const float*)d_in[8];
    const float* Wo = (const float*)d_in[9];
    const float* bo = (const float*)d_in[10];
    float* out = (float*)d_out;

    float *Qp, *Kp, *Vp, *Ctx;
    __nv_bfloat16 *Ahi, *Alo, *Whi, *Wlo;
    cudaGetSymbolAddress((void**)&Qp,  g_Qp);
    cudaGetSymbolAddress((void**)&Kp,  g_Kp);
    cudaGetSymbolAddress((void**)&Vp,  g_Vp);
    cudaGetSymbolAddress((void**)&Ctx, g_Ctx);
    cudaGetSymbolAddress((void**)&Ahi, g_Ahi);
    cudaGetSymbolAddress((void**)&Alo, g_Alo);
    cudaGetSymbolAddress((void**)&Whi, g_Whi);
    cudaGetSymbolAddress((void**)&Wlo, g_Wlo);

    const int CVT_A_BLOCKS = (MTOT * HH / 4) / 256;  // 4096
    const int CVT_W_BLOCKS = (HH * HH / 4) / 256;    // 1024
    dim3 blk(256);
    dim3 gg(HH / 64, MTOT / 128);                    // (16, 32)

    // Q projection
    cvt_split_kernel<<<CVT_A_BLOCKS, blk>>>(q, Ahi, Alo);
    cvt_split_kernel<<<CVT_W_BLOCKS, blk>>>(Wq, Whi, Wlo);
    gemm_mma_kernel<1><<<gg, blk>>>(Ahi, Alo, Whi, Wlo, bq, Qp);
    // K projection
    cvt_split_kernel<<<CVT_A_BLOCKS, blk>>>(k, Ahi, Alo);
    cvt_split_kernel<<<CVT_W_BLOCKS, blk>>>(Wk, Whi, Wlo);
    gemm_mma_kernel<1><<<gg, blk>>>(Ahi, Alo, Whi, Wlo, bk, Kp);
    // V projection
    cvt_split_kernel<<<CVT_A_BLOCKS, blk>>>(v, Ahi, Alo);
    cvt_split_kernel<<<CVT_W_BLOCKS, blk>>>(Wv, Whi, Wlo);
    gemm_mma_kernel<1><<<gg, blk>>>(Ahi, Alo, Whi, Wlo, bv, Vp);
    // Attention
    attn_kernel<<<dim3(SS / 64, BB * NH), blk>>>();
    // Output projection
    cvt_split_kernel<<<CVT_A_BLOCKS, blk>>>(Ctx, Ahi, Alo);
    cvt_split_kernel<<<CVT_W_BLOCKS, blk>>>(Wo, Whi, Wlo);
    gemm_mma_kernel<0><<<gg, blk>>>(Ahi, Alo, Whi, Wlo, bo, out);
}

// round 9
// speedup vs baseline: 2.7346x; 1.8199x over previous
#include <cuda_runtime.h>
#include <cuda_bf16.h>
#include <cstdint>
#include <math.h>

// Problem constants
#define BB   2
#define SS   2048
#define HH   1024
#define NH   16
#define HD   64
#define MTOT (BB*SS)   // 4096

// Scratch (device globals: allocation-free per harness rules)
// bf16 split pairs
__device__ __nv_bfloat16 g_Qhi[BB*NH*SS*HD];  // [B,nh,S,hd]
__device__ __nv_bfloat16 g_Qlo[BB*NH*SS*HD];
__device__ __nv_bfloat16 g_Khi[BB*NH*SS*HD];
__device__ __nv_bfloat16 g_Klo[BB*NH*SS*HD];
__device__ __nv_bfloat16 g_Vhi[BB*NH*SS*HD];
__device__ __nv_bfloat16 g_Vlo[BB*NH*SS*HD];
__device__ __nv_bfloat16 g_Ahi[MTOT*HH];      // GEMM A staging ([MTOT,HH])
__device__ __nv_bfloat16 g_Alo[MTOT*HH];
__device__ __nv_bfloat16 g_Whi[HH*HH];
__device__ __nv_bfloat16 g_Wlo[HH*HH];

// ---------------------------------------------------------------------------
// PTX helpers
// ---------------------------------------------------------------------------
__device__ __forceinline__ void cp16(unsigned dst, const void* src) {
    asm volatile("cp.async.cg.shared.global [%0], [%1], 16;"
                 :: "r"(dst), "l"(src));
}

__device__ __forceinline__ void cp_commit_wait() {
    asm volatile("cp.async.commit_group;");
    asm volatile("cp.async.wait_group 0;");
}

__device__ __forceinline__ void ldsm4(unsigned (&r)[4], unsigned addr) {
    asm volatile("ldmatrix.sync.aligned.m8n8.x4.shared.b16 {%0,%1,%2,%3}, [%4];"
                 : "=r"(r[0]), "=r"(r[1]), "=r"(r[2]), "=r"(r[3]) : "r"(addr));
}

__device__ __forceinline__ void ldsm4t(unsigned (&r)[4], unsigned addr) {
    asm volatile("ldmatrix.sync.aligned.m8n8.x4.trans.shared.b16 {%0,%1,%2,%3}, [%4];"
                 : "=r"(r[0]), "=r"(r[1]), "=r"(r[2]), "=r"(r[3]) : "r"(addr));
}

__device__ __forceinline__ void mma16816(float (&c)[4], const unsigned (&a)[4],
                                         unsigned b0, unsigned b1) {
    asm volatile("mma.sync.aligned.m16n8k16.row.col.f32.bf16.bf16.f32 "
                 "{%0,%1,%2,%3},{%4,%5,%6,%7},{%8,%9},{%0,%1,%2,%3};"
                 : "+f"(c[0]), "+f"(c[1]), "+f"(c[2]), "+f"(c[3])
                 : "r"(a[0]), "r"(a[1]), "r"(a[2]), "r"(a[3]), "r"(b0), "r"(b1));
}

// fp32 pair -> packed bf16x2 (round-nearest)
__device__ __forceinline__ unsigned pack_bf(float x, float y) {
    __nv_bfloat162 t = __float22bfloat162_rn(make_float2(x, y));
    return *(unsigned*)&t;
}

// ---------------------------------------------------------------------------
// fp32 -> (bf16 hi, bf16 lo) split (for the raw inputs and weights).
// ---------------------------------------------------------------------------
__global__ void cvt_split_kernel(const float* __restrict__ x,
                                 __nv_bfloat16* __restrict__ hi,
                                 __nv_bfloat16* __restrict__ lo)
{
    int i = blockIdx.x * blockDim.x + threadIdx.x;   // float4 index
    float4 v = ((const float4*)x)[i];

    __nv_bfloat16 h0 = __float2bfloat16(v.x);
    __nv_bfloat16 h1 = __float2bfloat16(v.y);
    __nv_bfloat16 h2 = __float2bfloat16(v.z);
    __nv_bfloat16 h3 = __float2bfloat16(v.w);
    __nv_bfloat16 l0 = __float2bfloat16(v.x - __bfloat162float(h0));
    __nv_bfloat16 l1 = __float2bfloat16(v.y - __bfloat162float(h1));
    __nv_bfloat16 l2 = __float2bfloat16(v.z - __bfloat162float(h2));
    __nv_bfloat16 l3 = __float2bfloat16(v.w - __bfloat162float(h3));

    __nv_bfloat162* hp = (__nv_bfloat162*)hi;
    __nv_bfloat162* lp = (__nv_bfloat162*)lo;
    hp[2*i]   = __nv_bfloat162(h0, h1);
    hp[2*i+1] = __nv_bfloat162(h2, h3);
    lp[2*i]   = __nv_bfloat162(l0, l1);
    lp[2*i+1] = __nv_bfloat162(l2, l3);
}

// ---------------------------------------------------------------------------
// Tensor-core NT GEMM via bf16 split: C[m,n] = sum_k A[m,k]*W[n,k] + bias[n]
// MODE 0: C fp32 row-major [MTOT,HH] (final output).
// MODE 1: C written as bf16 hi/lo pair to [B,nh,S,hd] split-head layout.
// ---------------------------------------------------------------------------
template<int MODE>
__global__ __launch_bounds__(256, 2)
void gemm_mma_kernel(const __nv_bfloat16* __restrict__ Ahi,
                     const __nv_bfloat16* __restrict__ Alo,
                     const __nv_bfloat16* __restrict__ Whi,
                     const __nv_bfloat16* __restrict__ Wlo,
                     const float* __restrict__ bias,
                     float* __restrict__ C,
                     __nv_bfloat16* __restrict__ Chi,
                     __nv_bfloat16* __restrict__ Clo)
{
    __shared__ __align__(128) char sm[49152];
    const unsigned sbase = (unsigned)__cvta_generic_to_shared(sm);
    const unsigned sAhi = sbase;
    const unsigned sAlo = sbase + 16384;
    const unsigned sBhi = sbase + 32768;
    const unsigned sBlo = sbase + 40960;

    const int tid  = threadIdx.x;
    const int lane = tid & 31;
    const int warp = tid >> 5;
    const int wm0  = (warp >> 1) * 32;
    const int wn0  = (warp & 1) * 32;
    const int m0   = blockIdx.y * 128;
    const int n0   = blockIdx.x * 64;

    float acc[2][4][4] = {};

    const int a_r   = lane & 15;
    const int a_kh  = lane >> 4;
    const int b_r   = (lane & 7) + ((lane >> 4) << 3);
    const int b_kh  = (lane >> 3) & 1;

    for (int k0 = 0; k0 < HH; k0 += 64) {
        __syncthreads();
        #pragma unroll
        for (int i = 0; i < 4; i++) {
            int e = tid + i * 256;
            int r = e >> 3, c = e & 7;
            unsigned soff = (unsigned)(r * 128 + ((c ^ (r & 7)) << 4));
            cp16(sAhi + soff, Ahi + (size_t)(m0 + r) * HH + k0 + c * 8);
            cp16(sAlo + soff, Alo + (size_t)(m0 + r) * HH + k0 + c * 8);
        }
        #pragma unroll
        for (int i = 0; i < 2; i++) {
            int e = tid + i * 256;
            int r = e >> 3, c = e & 7;
            unsigned soff = (unsigned)(r * 128 + ((c ^ (r & 7)) << 4));
            cp16(sBhi + soff, Whi + (size_t)(n0 + r) * HH + k0 + c * 8);
            cp16(sBlo + soff, Wlo + (size_t)(n0 + r) * HH + k0 + c * 8);
        }
        cp_commit_wait();
        __syncthreads();

        #pragma unroll
        for (int kk = 0; kk < 4; kk++) {
            unsigned fAh[2][4], fAl[2][4], fBh[2][4], fBl[2][4];
            #pragma unroll
            for (int mt = 0; mt < 2; mt++) {
                int r = wm0 + mt * 16 + a_r;
                int c = kk * 2 + a_kh;
                unsigned off = (unsigned)(r * 128 + ((c ^ (r & 7)) << 4));
                ldsm4(fAh[mt], sAhi + off);
                ldsm4(fAl[mt], sAlo + off);
            }
            #pragma unroll
            for (int nt2 = 0; nt2 < 2; nt2++) {
                int r = wn0 + nt2 * 16 + b_r;
                int c = kk * 2 + b_kh;
                unsigned off = (unsigned)(r * 128 + ((c ^ (r & 7)) << 4));
                ldsm4(fBh[nt2], sBhi + off);
                ldsm4(fBl[nt2], sBlo + off);
            }
            #pragma unroll
            for (int mt = 0; mt < 2; mt++) {
                #pragma unroll
                for (int nt = 0; nt < 4; nt++) {
                    int n2 = nt >> 1, p = (nt & 1) * 2;
                    mma16816(acc[mt][nt], fAh[mt], fBh[n2][p], fBh[n2][p+1]);
                    mma16816(acc[mt][nt], fAh[mt], fBl[n2][p], fBl[n2][p+1]);
                    mma16816(acc[mt][nt], fAl[mt], fBh[n2][p], fBh[n2][p+1]);
                }
            }
        }
    }

    const int g = lane >> 2, q = lane & 3;
    #pragma unroll
    for (int mt = 0; mt < 2; mt++) {
        #pragma unroll
        for (int nt = 0; nt < 4; nt++) {
            int col = n0 + wn0 + nt * 8 + q * 2;
            float b0 = bias[col], b1 = bias[col + 1];
            #pragma unroll
            for (int half = 0; half < 2; half++) {
                int row = m0 + wm0 + mt * 16 + g + half * 8;
                float v0 = acc[mt][nt][half * 2]     + b0;
                float v1 = acc[mt][nt][half * 2 + 1] + b1;
                if (MODE == 0) {
                    *(float2*)&C[(size_t)row * HH + col] = make_float2(v0, v1);
                } else {
                    int b = row >> 11, s = row & 2047;
                    int h = col >> 6,  d = col & 63;
                    size_t idx = (((size_t)(b * NH + h)) * SS + s) * HD + d;
                    __nv_bfloat162 hh = __float22bfloat162_rn(make_float2(v0, v1));
                    *(__nv_bfloat162*)&Chi[idx] = hh;
                    __nv_bfloat162 ll = __float22bfloat162_rn(make_float2(
                        v0 - __bfloat162float(hh.x), v1 - __bfloat162float(hh.y)));
                    *(__nv_bfloat162*)&Clo[idx] = ll;
                }
            }
        }
    }
}

// ---------------------------------------------------------------------------
// HMMA flash attention (bf16 split, fp32 softmax/accum).
// Block: 256 threads (8 warps), q-tile 128 (m16/warp), kt tiles of 64 seq.
// smem 32KB union: Q-stage (hi|lo 16K each) then per-kt K/V hi/lo 8K each.
// Epilogue writes O as bf16 hi/lo into g_Ahi/g_Alo ([B,S,H] row-major).
// ---------------------------------------------------------------------------
__global__ __launch_bounds__(256)
void attn_mma_kernel()
{
    __shared__ __align__(128) char sm[32768];
    const unsigned sbase = (unsigned)__cvta_generic_to_shared(sm);

    const int tid  = threadIdx.x;
    const int lane = tid & 31;
    const int w    = tid >> 5;          // 0..7
    const int qt   = blockIdx.x;        // 0..15 (q tiles of 128)
    const int bh   = blockIdx.y;        // 0..31
    const size_t head_base = (size_t)bh * SS * HD;

    // ---- Stage Q tile (128 x 64 hi/lo) and pull fragments into registers
    {
        const __nv_bfloat16* Qh = g_Qhi + head_base + (size_t)qt * 128 * HD;
        const __nv_bfloat16* Ql = g_Qlo + head_base + (size_t)qt * 128 * HD;
        #pragma unroll
        for (int i = 0; i < 4; i++) {
            int e = tid + i * 256;
            int r = e >> 3, c = e & 7;
            unsigned soff = (unsigned)(r * 128 + ((c ^ (r & 7)) << 4));
            cp16(sbase + soff,         Qh + (size_t)r * HD + c * 8);
            cp16(sbase + 16384 + soff, Ql + (size_t)r * HD + c * 8);
        }
        cp_commit_wait();
        __syncthreads();
    }

    const int a_r  = lane & 15;
    const int a_kh = lane >> 4;
    unsigned qh[4][4], ql[4][4];
    #pragma unroll
    for (int ks = 0; ks < 4; ks++) {
        int r = w * 16 + a_r;
        int c = ks * 2 + a_kh;
        unsigned off = (unsigned)(r * 128 + ((c ^ (r & 7)) << 4));
        ldsm4(qh[ks], sbase + off);
        ldsm4(ql[ks], sbase + 16384 + off);
    }

    float o[8][4] = {};                  // [d-tile nt][frag]: rows g,g+8 / cols 2q,2q+1
    float mrow[2] = {-1e30f, -1e30f};
    float lrow[2] = {0.0f, 0.0f};

    const unsigned sKhi = sbase;
    const unsigned sKlo = sbase + 8192;
    const unsigned sVhi = sbase + 16384;
    const unsigned sVlo = sbase + 24576;
    const int b_r  = (lane & 7) + ((lane >> 4) << 3);
    const int b_kh = (lane >> 3) & 1;

    for (int kt = 0; kt < SS / 64; kt++) {
        __syncthreads();                 // Q-frag loads / previous tile reads done
        const size_t tb = head_base + (size_t)kt * 64 * HD;
        #pragma unroll
        for (int i = 0; i < 2; i++) {
            int e = tid + i * 256;
            int r = e >> 3, c = e & 7;
            unsigned soff = (unsigned)(r * 128 + ((c ^ (r & 7)) << 4));
            size_t gi = tb + (size_t)r * HD + c * 8;
            cp16(sKhi + soff, g_Khi + gi);
            cp16(sKlo + soff, g_Klo + gi);
            cp16(sVhi + soff, g_Vhi + gi);
            cp16(sVlo + soff, g_Vlo + gi);
        }
        cp_commit_wait();
        __syncthreads();

        // ---- S = Q K^T (m16 x n64), bf16 split 3-pass, fp32 accum
        float sc[8][4] = {};
        #pragma unroll
        for (int ks = 0; ks < 4; ks++) {
            unsigned kh[4][4], kl[4][4];
            #pragma unroll
            for (int nt2 = 0; nt2 < 4; nt2++) {
                int r = nt2 * 16 + b_r;
                int c = ks * 2 + b_kh;
                unsigned off = (unsigned)(r * 128 + ((c ^ (r & 7)) << 4));
                ldsm4(kh[nt2], sKhi + off);
                ldsm4(kl[nt2], sKlo + off);
            }
            #pragma unroll
            for (int nt = 0; nt < 8; nt++) {
                int n2 = nt >> 1, p = (nt & 1) * 2;
                mma16816(sc[nt], qh[ks], kh[n2][p], kh[n2][p+1]);
                mma16816(sc[nt], qh[ks], kl[n2][p], kl[n2][p+1]);
                mma16816(sc[nt], ql[ks], kh[n2][p], kh[n2][p+1]);
            }
        }

        // ---- online softmax on fragment rows (g and g+8)
        #pragma unroll
        for (int rr = 0; rr < 2; rr++) {
            const int base = rr * 2;
            float tm = -1e30f;
            #pragma unroll
            for (int nt = 0; nt < 8; nt++) {
                sc[nt][base]     *= 0.125f;     // 1/sqrt(64)
                sc[nt][base + 1] *= 0.125f;
                tm = fmaxf(tm, fmaxf(sc[nt][base], sc[nt][base + 1]));
            }
            tm = fmaxf(tm, __shfl_xor_sync(0xffffffffu, tm, 1));
            tm = fmaxf(tm, __shfl_xor_sync(0xffffffffu, tm, 2));
            float mn   = fmaxf(mrow[rr], tm);
            float corr = __expf(mrow[rr] - mn);
            mrow[rr] = mn;
            float rs = 0.0f;
            #pragma unroll
            for (int nt = 0; nt < 8; nt++) {
                float p0 = __expf(sc[nt][base]     - mn);
                float p1 = __expf(sc[nt][base + 1] - mn);
                sc[nt][base] = p0; sc[nt][base + 1] = p1;
                rs += p0 + p1;
            }
            rs += __shfl_xor_sync(0xffffffffu, rs, 1);
            rs += __shfl_xor_sync(0xffffffffu, rs, 2);
            lrow[rr] = lrow[rr] * corr + rs;
            #pragma unroll
            for (int nt = 0; nt < 8; nt++) {
                o[nt][base]     *= corr;
                o[nt][base + 1] *= corr;
            }
        }

        // ---- O += P V  (P from S-fragments, split hi/lo; V via ldmatrix.trans)
        #pragma unroll
        for (int ks2 = 0; ks2 < 4; ks2++) {
            unsigned phi[4], plo[4];
            #pragma unroll
            for (int part = 0; part < 2; part++) {
                int nt = 2 * ks2 + part;
                #pragma unroll
                for (int hh = 0; hh < 2; hh++) {
                    float p0 = sc[nt][hh * 2], p1 = sc[nt][hh * 2 + 1];
                    __nv_bfloat162 h2 = __float22bfloat162_rn(make_float2(p0, p1));
                    phi[part * 2 + hh] = *(unsigned*)&h2;
                    plo[part * 2 + hh] = pack_bf(p0 - __bfloat162float(h2.x),
                                                 p1 - __bfloat162float(h2.y));
                }
            }
            #pragma unroll
            for (int dt = 0; dt < 4; dt++) {
                int r = ks2 * 16 + (lane & 15);
                int c = dt * 2 + (lane >> 4);
                unsigned off = (unsigned)(r * 128 + ((c ^ (r & 7)) << 4));
                unsigned vh[4], vl[4];
                ldsm4t(vh, sVhi + off);
                ldsm4t(vl, sVlo + off);
                mma16816(o[2*dt],     phi, vh[0], vh[1]);
                mma16816(o[2*dt],     phi, vl[0], vl[1]);
                mma16816(o[2*dt],     plo, vh[0], vh[1]);
                mma16816(o[2*dt + 1], phi, vh[2], vh[3]);
                mma16816(o[2*dt + 1], phi, vl[2], vl[3]);
                mma16816(o[2*dt + 1], plo, vh[2], vh[3]);
            }
        }
    }

    // ---- epilogue: normalize, write bf16 hi/lo into GEMM-A staging [B,S,H]
    const int b = bh >> 4, h = bh & 15;
    const int g = lane >> 2, q = lane & 3;
    const float inv0 = 1.0f / lrow[0];
    const float inv1 = 1.0f / lrow[1];
    const int row0 = qt * 128 + w * 16 + g;
    #pragma unroll
    for (int nt = 0; nt < 8; nt++) {
        int d = h * 64 + nt * 8 + q * 2;
        size_t i0 = ((size_t)(b * SS + row0))     * HH + d;
        size_t i1 = ((size_t)(b * SS + row0 + 8)) * HH + d;
        float v0 = o[nt][0] * inv0, v1 = o[nt][1] * inv0;
        float v2 = o[nt][2] * inv1, v3 = o[nt][3] * inv1;
        __nv_bfloat162 h2a = __float22bfloat162_rn(make_float2(v0, v1));
        *(__nv_bfloat162*)&g_Ahi[i0] = h2a;
        *(__nv_bfloat162*)&g_Alo[i0] = __float22bfloat162_rn(make_float2(
            v0 - __bfloat162float(h2a.x), v1 - __bfloat162float(h2a.y)));
        __nv_bfloat162 h2b = __float22bfloat162_rn(make_float2(v2, v3));
        *(__nv_bfloat162*)&g_Ahi[i1] = h2b;
        *(__nv_bfloat162*)&g_Alo[i1] = __float22bfloat162_rn(make_float2(
            v2 - __bfloat162float(h2b.x), v3 - __bfloat162float(h2b.y)));
    }
}

// ---------------------------------------------------------------------------
extern "C" void kernel_launch(void* const* d_in, const int* in_sizes, int n_in,
                              void* d_out, int out_size)
{
    const float* q  = (const float*)d_in[0];
    const float* k  = (const float*)d_in[1];
    const float* v  = (const float*)d_in[2];
    const float* Wq = (const float*)d_in[3];
    const float* bq = (const float*)d_in[4];
    const float* Wk = (const float*)d_in[5];
    const float* bk = (const float*)d_in[6];
    const float* Wv = (const float*)d_in[7];
    const float* bv = (const float*)d_in[8];
    const float* Wo = (const float*)d_in[9];
    const float* bo = (const float*)d_in[10];
    float* out = (float*)d_out;

    __nv_bfloat16 *Qhi, *Qlo, *Khi, *Klo, *Vhi, *Vlo, *Ahi, *Alo, *Whi, *Wlo;
    cudaGetSymbolAddress((void**)&Qhi, g_Qhi);
    cudaGetSymbolAddress((void**)&Qlo, g_Qlo);
    cudaGetSymbolAddress((void**)&Khi, g_Khi);
    cudaGetSymbolAddress((void**)&Klo, g_Klo);
    cudaGetSymbolAddress((void**)&Vhi, g_Vhi);
    cudaGetSymbolAddress((void**)&Vlo, g_Vlo);
    cudaGetSymbolAddress((void**)&Ahi, g_Ahi);
    cudaGetSymbolAddress((void**)&Alo, g_Alo);
    cudaGetSymbolAddress((void**)&Whi, g_Whi);
    cudaGetSymbolAddress((void**)&Wlo, g_Wlo);

    const int CVT_A_BLOCKS = (MTOT * HH / 4) / 256;  // 4096
    const int CVT_W_BLOCKS = (HH * HH / 4) / 256;    // 1024
    dim3 blk(256);
    dim3 gg(HH / 64, MTOT / 128);                    // (16, 32)

    // Q projection -> bf16 split heads
    cvt_split_kernel<<<CVT_A_BLOCKS, blk>>>(q, Ahi, Alo);
    cvt_split_kernel<<<CVT_W_BLOCKS, blk>>>(Wq, Whi, Wlo);
    gemm_mma_kernel<1><<<gg, blk>>>(Ahi, Alo, Whi, Wlo, bq, nullptr, Qhi, Qlo);
    // K projection
    cvt_split_kernel<<<CVT_A_BLOCKS, blk>>>(k, Ahi, Alo);
    cvt_split_kernel<<<CVT_W_BLOCKS, blk>>>(Wk, Whi, Wlo);
    gemm_mma_kernel<1><<<gg, blk>>>(Ahi, Alo, Whi, Wlo, bk, nullptr, Khi, Klo);
    // V projection
    cvt_split_kernel<<<CVT_A_BLOCKS, blk>>>(v, Ahi, Alo);
    cvt_split_kernel<<<CVT_W_BLOCKS, blk>>>(Wv, Whi, Wlo);
    gemm_mma_kernel<1><<<gg, blk>>>(Ahi, Alo, Whi, Wlo, bv, nullptr, Vhi, Vlo);
    // Attention (writes O as bf16 split directly into Ahi/Alo)
    attn_mma_kernel<<<dim3(SS / 128, BB * NH), blk>>>();
    // Output projection
    cvt_split_kernel<<<CVT_W_BLOCKS, blk>>>(Wo, Whi, Wlo);
    gemm_mma_kernel<0><<<gg, blk>>>(Ahi, Alo, Whi, Wlo, bo, out, nullptr, nullptr);
}

// round 11
// speedup vs baseline: 2.7453x; 1.0039x over previous
#include <cuda_runtime.h>
#include <cuda_bf16.h>
#include <cstdint>
#include <math.h>

// Problem constants
#define BB   2
#define SS   2048
#define HH   1024
#define NH   16
#define HD   64
#define MTOT (BB*SS)   // 4096

// Scratch (device globals: allocation-free per harness rules)
// bf16 split pairs
__device__ __nv_bfloat16 g_Qhi[BB*NH*SS*HD];  // [B,nh,S,hd]
__device__ __nv_bfloat16 g_Qlo[BB*NH*SS*HD];
__device__ __nv_bfloat16 g_Khi[BB*NH*SS*HD];
__device__ __nv_bfloat16 g_Klo[BB*NH*SS*HD];
__device__ __nv_bfloat16 g_Vhi[BB*NH*SS*HD];
__device__ __nv_bfloat16 g_Vlo[BB*NH*SS*HD];
__device__ __nv_bfloat16 g_Ahi[MTOT*HH];      // GEMM A staging ([MTOT,HH])
__device__ __nv_bfloat16 g_Alo[MTOT*HH];
__device__ __nv_bfloat16 g_Whi[HH*HH];
__device__ __nv_bfloat16 g_Wlo[HH*HH];

// ---------------------------------------------------------------------------
// PTX helpers
// ---------------------------------------------------------------------------
__device__ __forceinline__ void cp16(unsigned dst, const void* src) {
    asm volatile("cp.async.cg.shared.global [%0], [%1], 16;"
                 :: "r"(dst), "l"(src));
}

__device__ __forceinline__ void cp_commit_wait() {
    asm volatile("cp.async.commit_group;");
    asm volatile("cp.async.wait_group 0;");
}

__device__ __forceinline__ void ldsm4(unsigned (&r)[4], unsigned addr) {
    asm volatile("ldmatrix.sync.aligned.m8n8.x4.shared.b16 {%0,%1,%2,%3}, [%4];"
                 : "=r"(r[0]), "=r"(r[1]), "=r"(r[2]), "=r"(r[3]) : "r"(addr));
}

__device__ __forceinline__ void ldsm4t(unsigned (&r)[4], unsigned addr) {
    asm volatile("ldmatrix.sync.aligned.m8n8.x4.trans.shared.b16 {%0,%1,%2,%3}, [%4];"
                 : "=r"(r[0]), "=r"(r[1]), "=r"(r[2]), "=r"(r[3]) : "r"(addr));
}

__device__ __forceinline__ void mma16816(float (&c)[4], const unsigned (&a)[4],
                                         unsigned b0, unsigned b1) {
    asm volatile("mma.sync.aligned.m16n8k16.row.col.f32.bf16.bf16.f32 "
                 "{%0,%1,%2,%3},{%4,%5,%6,%7},{%8,%9},{%0,%1,%2,%3};"
                 : "+f"(c[0]), "+f"(c[1]), "+f"(c[2]), "+f"(c[3])
                 : "r"(a[0]), "r"(a[1]), "r"(a[2]), "r"(a[3]), "r"(b0), "r"(b1));
}

// fp32 pair -> packed bf16x2 (round-nearest)
__device__ __forceinline__ unsigned pack_bf(float x, float y) {
    __nv_bfloat162 t = __float22bfloat162_rn(make_float2(x, y));
    return *(unsigned*)&t;
}

// ---------------------------------------------------------------------------
// fp32 -> (bf16 hi, bf16 lo) split (for the raw inputs and weights).
// ---------------------------------------------------------------------------
__global__ void cvt_split_kernel(const float* __restrict__ x,
                                 __nv_bfloat16* __restrict__ hi,
                                 __nv_bfloat16* __restrict__ lo)
{
    int i = blockIdx.x * blockDim.x + threadIdx.x;   // float4 index
    float4 v = ((const float4*)x)[i];

    __nv_bfloat16 h0 = __float2bfloat16(v.x);
    __nv_bfloat16 h1 = __float2bfloat16(v.y);
    __nv_bfloat16 h2 = __float2bfloat16(v.z);
    __nv_bfloat16 h3 = __float2bfloat16(v.w);
    __nv_bfloat16 l0 = __float2bfloat16(v.x - __bfloat162float(h0));
    __nv_bfloat16 l1 = __float2bfloat16(v.y - __bfloat162float(h1));
    __nv_bfloat16 l2 = __float2bfloat16(v.z - __bfloat162float(h2));
    __nv_bfloat16 l3 = __float2bfloat16(v.w - __bfloat162float(h3));

    __nv_bfloat162* hp = (__nv_bfloat162*)hi;
    __nv_bfloat162* lp = (__nv_bfloat162*)lo;
    hp[2*i]   = __nv_bfloat162(h0, h1);
    hp[2*i+1] = __nv_bfloat162(h2, h3);
    lp[2*i]   = __nv_bfloat162(l0, l1);
    lp[2*i+1] = __nv_bfloat162(l2, l3);
}

// ---------------------------------------------------------------------------
// Tensor-core NT GEMM via bf16 split: C[m,n] = sum_k A[m,k]*W[n,k] + bias[n]
// MODE 0: C fp32 row-major [MTOT,HH] (final output).
// MODE 1: C written as bf16 hi/lo pair to [B,nh,S,hd] split-head layout.
// ---------------------------------------------------------------------------
template<int MODE>
__global__ __launch_bounds__(256, 2)
void gemm_mma_kernel(const __nv_bfloat16* __restrict__ Ahi,
                     const __nv_bfloat16* __restrict__ Alo,
                     const __nv_bfloat16* __restrict__ Whi,
                     const __nv_bfloat16* __restrict__ Wlo,
                     const float* __restrict__ bias,
                     float* __restrict__ C,
                     __nv_bfloat16* __restrict__ Chi,
                     __nv_bfloat16* __restrict__ Clo)
{
    __shared__ __align__(128) char sm[49152];
    const unsigned sbase = (unsigned)__cvta_generic_to_shared(sm);
    const unsigned sAhi = sbase;
    const unsigned sAlo = sbase + 16384;
    const unsigned sBhi = sbase + 32768;
    const unsigned sBlo = sbase + 40960;

    const int tid  = threadIdx.x;
    const int lane = tid & 31;
    const int warp = tid >> 5;
    const int wm0  = (warp >> 1) * 32;
    const int wn0  = (warp & 1) * 32;
    const int m0   = blockIdx.y * 128;
    const int n0   = blockIdx.x * 64;

    float acc[2][4][4] = {};

    const int a_r   = lane & 15;
    const int a_kh  = lane >> 4;
    const int b_r   = (lane & 7) + ((lane >> 4) << 3);
    const int b_kh  = (lane >> 3) & 1;

    for (int k0 = 0; k0 < HH; k0 += 64) {
        __syncthreads();
        #pragma unroll
        for (int i = 0; i < 4; i++) {
            int e = tid + i * 256;
            int r = e >> 3, c = e & 7;
            unsigned soff = (unsigned)(r * 128 + ((c ^ (r & 7)) << 4));
            cp16(sAhi + soff, Ahi + (size_t)(m0 + r) * HH + k0 + c * 8);
            cp16(sAlo + soff, Alo + (size_t)(m0 + r) * HH + k0 + c * 8);
        }
        #pragma unroll
        for (int i = 0; i < 2; i++) {
            int e = tid + i * 256;
            int r = e >> 3, c = e & 7;
            unsigned soff = (unsigned)(r * 128 + ((c ^ (r & 7)) << 4));
            cp16(sBhi + soff, Whi + (size_t)(n0 + r) * HH + k0 + c * 8);
            cp16(sBlo + soff, Wlo + (size_t)(n0 + r) * HH + k0 + c * 8);
        }
        cp_commit_wait();
        __syncthreads();

        #pragma unroll
        for (int kk = 0; kk < 4; kk++) {
            unsigned fAh[2][4], fAl[2][4], fBh[2][4], fBl[2][4];
            #pragma unroll
            for (int mt = 0; mt < 2; mt++) {
                int r = wm0 + mt * 16 + a_r;
                int c = kk * 2 + a_kh;
                unsigned off = (unsigned)(r * 128 + ((c ^ (r & 7)) << 4));
                ldsm4(fAh[mt], sAhi + off);
                ldsm4(fAl[mt], sAlo + off);
            }
            #pragma unroll
            for (int nt2 = 0; nt2 < 2; nt2++) {
                int r = wn0 + nt2 * 16 + b_r;
                int c = kk * 2 + b_kh;
                unsigned off = (unsigned)(r * 128 + ((c ^ (r & 7)) << 4));
                ldsm4(fBh[nt2], sBhi + off);
                ldsm4(fBl[nt2], sBlo + off);
            }
            #pragma unroll
            for (int mt = 0; mt < 2; mt++) {
                #pragma unroll
                for (int nt = 0; nt < 4; nt++) {
                    int n2 = nt >> 1, p = (nt & 1) * 2;
                    mma16816(acc[mt][nt], fAh[mt], fBh[n2][p], fBh[n2][p+1]);
                    mma16816(acc[mt][nt], fAh[mt], fBl[n2][p], fBl[n2][p+1]);
                    mma16816(acc[mt][nt], fAl[mt], fBh[n2][p], fBh[n2][p+1]);
                }
            }
        }
    }

    const int g = lane >> 2, q = lane & 3;
    #pragma unroll
    for (int mt = 0; mt < 2; mt++) {
        #pragma unroll
        for (int nt = 0; nt < 4; nt++) {
            int col = n0 + wn0 + nt * 8 + q * 2;
            float b0 = bias[col], b1 = bias[col + 1];
            #pragma unroll
            for (int half = 0; half < 2; half++) {
                int row = m0 + wm0 + mt * 16 + g + half * 8;
                float v0 = acc[mt][nt][half * 2]     + b0;
                float v1 = acc[mt][nt][half * 2 + 1] + b1;
                if (MODE == 0) {
                    *(float2*)&C[(size_t)row * HH + col] = make_float2(v0, v1);
                } else {
                    int b = row >> 11, s = row & 2047;
                    int h = col >> 6,  d = col & 63;
                    size_t idx = (((size_t)(b * NH + h)) * SS + s) * HD + d;
                    __nv_bfloat162 hh = __float22bfloat162_rn(make_float2(v0, v1));
                    *(__nv_bfloat162*)&Chi[idx] = hh;
                    __nv_bfloat162 ll = __float22bfloat162_rn(make_float2(
                        v0 - __bfloat162float(hh.x), v1 - __bfloat162float(hh.y)));
                    *(__nv_bfloat162*)&Clo[idx] = ll;
                }
            }
        }
    }
}

// ---------------------------------------------------------------------------
// HMMA flash attention (bf16 split, fp32 softmax/accum).
// Block: 256 threads (8 warps), q-tile 128 (m16/warp), kt tiles of 64 seq.
// smem 32KB union: Q-stage (hi|lo 16K each) then per-kt K/V hi/lo 8K each.
// Epilogue writes O as bf16 hi/lo into g_Ahi/g_Alo ([B,S,H] row-major).
// ---------------------------------------------------------------------------
__global__ __launch_bounds__(256)
void attn_mma_kernel()
{
    __shared__ __align__(128) char sm[32768];
    const unsigned sbase = (unsigned)__cvta_generic_to_shared(sm);

    const int tid  = threadIdx.x;
    const int lane = tid & 31;
    const int w    = tid >> 5;          // 0..7
    const int qt   = blockIdx.x;        // 0..15 (q tiles of 128)
    const int bh   = blockIdx.y;        // 0..31
    const size_t head_base = (size_t)bh * SS * HD;

    // ---- Stage Q tile (128 x 64 hi/lo) and pull fragments into registers
    {
        const __nv_bfloat16* Qh = g_Qhi + head_base + (size_t)qt * 128 * HD;
        const __nv_bfloat16* Ql = g_Qlo + head_base + (size_t)qt * 128 * HD;
        #pragma unroll
        for (int i = 0; i < 4; i++) {
            int e = tid + i * 256;
            int r = e >> 3, c = e & 7;
            unsigned soff = (unsigned)(r * 128 + ((c ^ (r & 7)) << 4));
            cp16(sbase + soff,         Qh + (size_t)r * HD + c * 8);
            cp16(sbase + 16384 + soff, Ql + (size_t)r * HD + c * 8);
        }
        cp_commit_wait();
        __syncthreads();
    }

    const int a_r  = lane & 15;
    const int a_kh = lane >> 4;
    unsigned qh[4][4], ql[4][4];
    #pragma unroll
    for (int ks = 0; ks < 4; ks++) {
        int r = w * 16 + a_r;
        int c = ks * 2 + a_kh;
        unsigned off = (unsigned)(r * 128 + ((c ^ (r & 7)) << 4));
        ldsm4(qh[ks], sbase + off);
        ldsm4(ql[ks], sbase + 16384 + off);
    }

    float o[8][4] = {};                  // [d-tile nt][frag]: rows g,g+8 / cols 2q,2q+1
    float mrow[2] = {-1e30f, -1e30f};
    float lrow[2] = {0.0f, 0.0f};

    const unsigned sKhi = sbase;
    const unsigned sKlo = sbase + 8192;
    const unsigned sVhi = sbase + 16384;
    const unsigned sVlo = sbase + 24576;
    const int b_r  = (lane & 7) + ((lane >> 4) << 3);
    const int b_kh = (lane >> 3) & 1;

    for (int kt = 0; kt < SS / 64; kt++) {
        __syncthreads();                 // Q-frag loads / previous tile reads done
        const size_t tb = head_base + (size_t)kt * 64 * HD;
        #pragma unroll
        for (int i = 0; i < 2; i++) {
            int e = tid + i * 256;
            int r = e >> 3, c = e & 7;
            unsigned soff = (unsigned)(r * 128 + ((c ^ (r & 7)) << 4));
            size_t gi = tb + (size_t)r * HD + c * 8;
            cp16(sKhi + soff, g_Khi + gi);
            cp16(sKlo + soff, g_Klo + gi);
            cp16(sVhi + soff, g_Vhi + gi);
            cp16(sVlo + soff, g_Vlo + gi);
        }
        cp_commit_wait();
        __syncthreads();

        // ---- S = Q K^T (m16 x n64), bf16 split 3-pass, fp32 accum
        float sc[8][4] = {};
        #pragma unroll
        for (int ks = 0; ks < 4; ks++) {
            unsigned kh[4][4], kl[4][4];
            #pragma unroll
            for (int nt2 = 0; nt2 < 4; nt2++) {
                int r = nt2 * 16 + b_r;
                int c = ks * 2 + b_kh;
                unsigned off = (unsigned)(r * 128 + ((c ^ (r & 7)) << 4));
                ldsm4(kh[nt2], sKhi + off);
                ldsm4(kl[nt2], sKlo + off);
            }
            #pragma unroll
            for (int nt = 0; nt < 8; nt++) {
                int n2 = nt >> 1, p = (nt & 1) * 2;
                mma16816(sc[nt], qh[ks], kh[n2][p], kh[n2][p+1]);
                mma16816(sc[nt], qh[ks], kl[n2][p], kl[n2][p+1]);
                mma16816(sc[nt], ql[ks], kh[n2][p], kh[n2][p+1]);
            }
        }

        // ---- online softmax on fragment rows (g and g+8)
        #pragma unroll
        for (int rr = 0; rr < 2; rr++) {
            const int base = rr * 2;
            float tm = -1e30f;
            #pragma unroll
            for (int nt = 0; nt < 8; nt++) {
                sc[nt][base]     *= 0.125f;     // 1/sqrt(64)
                sc[nt][base + 1] *= 0.125f;
                tm = fmaxf(tm, fmaxf(sc[nt][base], sc[nt][base + 1]));
            }
            tm = fmaxf(tm, __shfl_xor_sync(0xffffffffu, tm, 1));
            tm = fmaxf(tm, __shfl_xor_sync(0xffffffffu, tm, 2));
            float mn   = fmaxf(mrow[rr], tm);
            float corr = __expf(mrow[rr] - mn);
            mrow[rr] = mn;
            float rs = 0.0f;
            #pragma unroll
            for (int nt = 0; nt < 8; nt++) {
                float p0 = __expf(sc[nt][base]     - mn);
                float p1 = __expf(sc[nt][base + 1] - mn);
                sc[nt][base] = p0; sc[nt][base + 1] = p1;
                rs += p0 + p1;
            }
            rs += __shfl_xor_sync(0xffffffffu, rs, 1);
            rs += __shfl_xor_sync(0xffffffffu, rs, 2);
            lrow[rr] = lrow[rr] * corr + rs;
            #pragma unroll
            for (int nt = 0; nt < 8; nt++) {
                o[nt][base]     *= corr;
                o[nt][base + 1] *= corr;
            }
        }

        // ---- O += P V  (P from S-fragments, split hi/lo; V via ldmatrix.trans)
        #pragma unroll
        for (int ks2 = 0; ks2 < 4; ks2++) {
            unsigned phi[4], plo[4];
            #pragma unroll
            for (int part = 0; part < 2; part++) {
                int nt = 2 * ks2 + part;
                #pragma unroll
                for (int hh = 0; hh < 2; hh++) {
                    float p0 = sc[nt][hh * 2], p1 = sc[nt][hh * 2 + 1];
                    __nv_bfloat162 h2 = __float22bfloat162_rn(make_float2(p0, p1));
                    phi[part * 2 + hh] = *(unsigned*)&h2;
                    plo[part * 2 + hh] = pack_bf(p0 - __bfloat162float(h2.x),
                                                 p1 - __bfloat162float(h2.y));
                }
            }
            #pragma unroll
            for (int dt = 0; dt < 4; dt++) {
                int r = ks2 * 16 + (lane & 15);
                int c = dt * 2 + (lane >> 4);
                unsigned off = (unsigned)(r * 128 + ((c ^ (r & 7)) << 4));
                unsigned vh[4], vl[4];
                ldsm4t(vh, sVhi + off);
                ldsm4t(vl, sVlo + off);
                mma16816(o[2*dt],     phi, vh[0], vh[1]);
                mma16816(o[2*dt],     phi, vl[0], vl[1]);
                mma16816(o[2*dt],     plo, vh[0], vh[1]);
                mma16816(o[2*dt + 1], phi, vh[2], vh[3]);
                mma16816(o[2*dt + 1], phi, vl[2], vl[3]);
                mma16816(o[2*dt + 1], plo, vh[2], vh[3]);
            }
        }
    }

    // ---- epilogue: normalize, write bf16 hi/lo into GEMM-A staging [B,S,H]
    const int b = bh >> 4, h = bh & 15;
    const int g = lane >> 2, q = lane & 3;
    const float inv0 = 1.0f / lrow[0];
    const float inv1 = 1.0f / lrow[1];
    const int row0 = qt * 128 + w * 16 + g;
    #pragma unroll
    for (int nt = 0; nt < 8; nt++) {
        int d = h * 64 + nt * 8 + q * 2;
        size_t i0 = ((size_t)(b * SS + row0))     * HH + d;
        size_t i1 = ((size_t)(b * SS + row0 + 8)) * HH + d;
        float v0 = o[nt][0] * inv0, v1 = o[nt][1] * inv0;
        float v2 = o[nt][2] * inv1, v3 = o[nt][3] * inv1;
        __nv_bfloat162 h2a = __float22bfloat162_rn(make_float2(v0, v1));
        *(__nv_bfloat162*)&g_Ahi[i0] = h2a;
        *(__nv_bfloat162*)&g_Alo[i0] = __float22bfloat162_rn(make_float2(
            v0 - __bfloat162float(h2a.x), v1 - __bfloat162float(h2a.y)));
        __nv_bfloat162 h2b = __float22bfloat162_rn(make_float2(v2, v3));
        *(__nv_bfloat162*)&g_Ahi[i1] = h2b;
        *(__nv_bfloat162*)&g_Alo[i1] = __float22bfloat162_rn(make_float2(
            v2 - __bfloat162float(h2b.x), v3 - __bfloat162float(h2b.y)));
    }
}

// ---------------------------------------------------------------------------
extern "C" void kernel_launch(void* const* d_in, const int* in_sizes, int n_in,
                              void* d_out, int out_size)
{
    const float* q  = (const float*)d_in[0];
    const float* k  = (const float*)d_in[1];
    const float* v  = (const float*)d_in[2];
    const float* Wq = (const float*)d_in[3];
    const float* bq = (const float*)d_in[4];
    const float* Wk = (const float*)d_in[5];
    const float* bk = (const float*)d_in[6];
    const float* Wv = (const float*)d_in[7];
    const float* bv = (const float*)d_in[8];
    const float* Wo = (const float*)d_in[9];
    const float* bo = (const float*)d_in[10];
    float* out = (float*)d_out;

    __nv_bfloat16 *Qhi, *Qlo, *Khi, *Klo, *Vhi, *Vlo, *Ahi, *Alo, *Whi, *Wlo;
    cudaGetSymbolAddress((void**)&Qhi, g_Qhi);
    cudaGetSymbolAddress((void**)&Qlo, g_Qlo);
    cudaGetSymbolAddress((void**)&Khi, g_Khi);
    cudaGetSymbolAddress((void**)&Klo, g_Klo);
    cudaGetSymbolAddress((void**)&Vhi, g_Vhi);
    cudaGetSymbolAddress((void**)&Vlo, g_Vlo);
    cudaGetSymbolAddress((void**)&Ahi, g_Ahi);
    cudaGetSymbolAddress((void**)&Alo, g_Alo);
    cudaGetSymbolAddress((void**)&Whi, g_Whi);
    cudaGetSymbolAddress((void**)&Wlo, g_Wlo);

    const int CVT_A_BLOCKS = (MTOT * HH / 4) / 256;  // 4096
    const int CVT_W_BLOCKS = (HH * HH / 4) / 256;    // 1024
    dim3 blk(256);
    dim3 gg(HH / 64, MTOT / 128);                    // (16, 32)

    // Q projection -> bf16 split heads
    cvt_split_kernel<<<CVT_A_BLOCKS, blk>>>(q, Ahi, Alo);
    cvt_split_kernel<<<CVT_W_BLOCKS, blk>>>(Wq, Whi, Wlo);
    gemm_mma_kernel<1><<<gg, blk>>>(Ahi, Alo, Whi, Wlo, bq, nullptr, Qhi, Qlo);
    // K projection
    cvt_split_kernel<<<CVT_A_BLOCKS, blk>>>(k, Ahi, Alo);
    cvt_split_kernel<<<CVT_W_BLOCKS, blk>>>(Wk, Whi, Wlo);
    gemm_mma_kernel<1><<<gg, blk>>>(Ahi, Alo, Whi, Wlo, bk, nullptr, Khi, Klo);
    // V projection
    cvt_split_kernel<<<CVT_A_BLOCKS, blk>>>(v, Ahi, Alo);
    cvt_split_kernel<<<CVT_W_BLOCKS, blk>>>(Wv, Whi, Wlo);
    gemm_mma_kernel<1><<<gg, blk>>>(Ahi, Alo, Whi, Wlo, bv, nullptr, Vhi, Vlo);
    // Attention (writes O as bf16 split directly into Ahi/Alo)
    attn_mma_kernel<<<dim3(SS / 128, BB * NH), blk>>>();
    // Output projection
    cvt_split_kernel<<<CVT_W_BLOCKS, blk>>>(Wo, Whi, Wlo);
    gemm_mma_kernel<0><<<gg, blk>>>(Ahi, Alo, Whi, Wlo, bo, out, nullptr, nullptr);
}